// round 6
// baseline (speedup 1.0000x reference)
#include <cuda_runtime.h>
#include <cstdint>

#define NN 50000
#define NE 800000

// ================= helpers =================
__device__ __forceinline__ uint32_t to_tf32(float x) {
    uint32_t r;
    asm("cvt.rna.tf32.f32 %0, %1;" : "=r"(r) : "f"(x));
    return r;
}

__device__ __forceinline__ void mma_tf32(float c[4], const uint32_t a[4], const uint32_t b[2]) {
    asm volatile(
        "mma.sync.aligned.m16n8k8.row.col.f32.tf32.tf32.f32 "
        "{%0,%1,%2,%3}, {%4,%5,%6,%7}, {%8,%9}, {%0,%1,%2,%3};"
        : "+f"(c[0]), "+f"(c[1]), "+f"(c[2]), "+f"(c[3])
        : "r"(a[0]), "r"(a[1]), "r"(a[2]), "r"(a[3]), "r"(b[0]), "r"(b[1]));
}

// ================= scratch =================
__device__ __align__(16) float g_agg[NN * 96];
__device__ __align__(16) float g_h1 [NN * 96];
__device__ __align__(16) float g_h2 [NN * 64];
__device__ __align__(16) float g_h3 [NN * 96];
__device__ __align__(16) float g_h4 [NN * 96];
__device__ __align__(16) float g_h5 [NN * 16];
__device__ __align__(16) float g_sum[96];
__device__ __align__(16) float g_sq [96];
__device__ __align__(16) float g_sc [5][96];
__device__ __align__(16) float g_sh [5][96];

// ================= edge kernel (atomic scatter, proven in R1) =================
__global__ void edge_kernel(const float* __restrict__ x,
                            const float* __restrict__ sc,
                            const float* __restrict__ sh,
                            const float* __restrict__ ea,
                            const int*   __restrict__ src,
                            const int*   __restrict__ dst,
                            const float* __restrict__ lw,
                            const float* __restrict__ lb,
                            float* __restrict__ agg)
{
    long long tid = (long long)blockIdx.x * blockDim.x + threadIdx.x;
    if (tid >= (long long)NE * 24) return;
    int i = (int)(tid / 24);
    int c = (int)(tid - (long long)i * 24);

    int   s = src[i];
    int   d = dst[i];
    float a = ea[i];

    float4 lw4 = reinterpret_cast<const float4*>(lw)[c];
    float4 lb4 = reinterpret_cast<const float4*>(lb)[c];
    float4 xv  = reinterpret_cast<const float4*>(x + (size_t)s * 96)[c];
    if (sc != nullptr) {
        float4 sc4 = reinterpret_cast<const float4*>(sc)[c];
        float4 sh4 = reinterpret_cast<const float4*>(sh)[c];
        xv.x = fmaf(xv.x, sc4.x, sh4.x);
        xv.y = fmaf(xv.y, sc4.y, sh4.y);
        xv.z = fmaf(xv.z, sc4.z, sh4.z);
        xv.w = fmaf(xv.w, sc4.w, sh4.w);
    }

    float4 m;
    m.x = fmaxf(fmaf(a, lw4.x, lb4.x) + xv.x, 0.0f);
    m.y = fmaxf(fmaf(a, lw4.y, lb4.y) + xv.y, 0.0f);
    m.z = fmaxf(fmaf(a, lw4.z, lb4.z) + xv.z, 0.0f);
    m.w = fmaxf(fmaf(a, lw4.w, lb4.w) + xv.w, 0.0f);

    float* p = agg + (size_t)d * 96 + c * 4;
    asm volatile("red.global.add.v4.f32 [%0], {%1, %2, %3, %4};"
                 :: "l"(p), "f"(m.x), "f"(m.y), "f"(m.z), "f"(m.w) : "memory");
}

// ================= tf32x3 mma.sync GEMM + bias + ReLU + BN stats =================
// H[M,N] = relu( In[M,K] @ W[K,N] + bias );  column sum/sumsq -> gsum/gsq.
// In row: affine(A)(+Aadd) for cols<K1; affine2(B2) for cols>=K1 (concat).
// tf32x3: X = hi + lo (both tf32); A@B = Ah Bh + Ah Bl + Al Bh (fp32 acc).
// Fragment-permuted SMEM layouts (validated in R5).
template<int N, int K>
__global__ void __launch_bounds__(256)
gemm_mma(const float* __restrict__ A,
         const float* __restrict__ scA, const float* __restrict__ shA,
         const float* __restrict__ Aadd,
         const float* __restrict__ B2,
         const float* __restrict__ scB, const float* __restrict__ shB,
         int K1,
         const float* __restrict__ W, const float* __restrict__ bias,
         float* __restrict__ H,
         float* __restrict__ gsum, float* __restrict__ gsq,
         int M)
{
    constexpr int CHUNK  = (K > 96) ? 32 : K;      // A k-chunk resident size
    constexpr int NFRAG  = N / 16;                 // n-frags per warp (2 warp cols)
    constexpr int A_FLOATS = 128 * CHUNK;          // per hi/lo copy
    constexpr int B_FLOATS = K * N;

    extern __shared__ float smem[];
    float* As = smem;                              // [2][A_FLOATS] hi, lo
    float* Bs = smem + 2 * A_FLOATS;               // [2][B_FLOATS] hi, lo
    __shared__ float s_sum[N];
    __shared__ float s_sq [N];

    const int tid  = threadIdx.x;
    const int wid  = tid >> 5;
    const int lane = tid & 31;
    const int wm   = wid & 3;                      // warp row (32 rows each)
    const int wn   = wid >> 2;                     // warp col (N/2 each)
    const int g    = lane >> 2;
    const int t    = lane & 3;
    const int m0   = blockIdx.x * 128;

    for (int i = tid; i < N; i += 256) { s_sum[i] = 0.f; s_sq[i] = 0.f; }

    // ---- load B = W^T permuted, hi/lo ----
    uint32_t* Bu = reinterpret_cast<uint32_t*>(Bs);
    constexpr int NC4 = N / 4;
    for (int i = tid; i < K * NC4; i += 256) {
        int k  = i / NC4;
        int n0 = (i % NC4) * 4;
        float4 v = *reinterpret_cast<const float4*>(W + (size_t)k * N + n0);
        float vv[4] = {v.x, v.y, v.z, v.w};
        int kb = k >> 3, kk = k & 7;
        int nb = n0 >> 3, nn0 = n0 & 7;
        int base = (kb * (N / 8) + nb) * 64 + (kk >> 2);
#pragma unroll
        for (int j = 0; j < 4; j++) {
            uint32_t hib = to_tf32(vv[j]);
            float    hif = __uint_as_float(hib);
            uint32_t lob = to_tf32(vv[j] - hif);
            int addr = base + (((nn0 + j) * 4 + (kk & 3))) * 2;
            Bu[addr]            = hib;
            Bu[B_FLOATS + addr] = lob;
        }
    }

    // ---- accumulators ----
    float acc[2][NFRAG][4];
#pragma unroll
    for (int mf = 0; mf < 2; mf++)
#pragma unroll
        for (int nf = 0; nf < NFRAG; nf++)
#pragma unroll
            for (int q = 0; q < 4; q++) acc[mf][nf][q] = 0.f;

    uint32_t* Au = reinterpret_cast<uint32_t*>(As);
    constexpr int C4 = CHUNK / 4;

    for (int kc = 0; kc < K; kc += CHUNK) {
        if (kc > 0) __syncthreads();               // protect As reuse

        // ---- load A chunk: affine / add / concat, hi/lo permuted ----
        for (int i = tid; i < 128 * C4; i += 256) {
            int row = i / C4;
            int lc  = (i % C4) * 4;
            int gc  = kc + lc;
            int grow = m0 + row;
            float4 v = make_float4(0.f, 0.f, 0.f, 0.f);
            if (grow < M) {
                if (B2 != nullptr && gc >= K1) {
                    int cc = gc - K1;
                    v = *reinterpret_cast<const float4*>(B2 + (size_t)grow * (K - K1) + cc);
                    float4 s4 = *reinterpret_cast<const float4*>(scB + cc);
                    float4 h4 = *reinterpret_cast<const float4*>(shB + cc);
                    v.x = fmaf(v.x, s4.x, h4.x); v.y = fmaf(v.y, s4.y, h4.y);
                    v.z = fmaf(v.z, s4.z, h4.z); v.w = fmaf(v.w, s4.w, h4.w);
                } else {
                    v = *reinterpret_cast<const float4*>(A + (size_t)grow * K1 + gc);
                    if (scA != nullptr) {
                        float4 s4 = *reinterpret_cast<const float4*>(scA + gc);
                        float4 h4 = *reinterpret_cast<const float4*>(shA + gc);
                        v.x = fmaf(v.x, s4.x, h4.x); v.y = fmaf(v.y, s4.y, h4.y);
                        v.z = fmaf(v.z, s4.z, h4.z); v.w = fmaf(v.w, s4.w, h4.w);
                    }
                    if (Aadd != nullptr) {
                        float4 v2 = *reinterpret_cast<const float4*>(Aadd + (size_t)grow * K1 + gc);
                        v.x += v2.x; v.y += v2.y; v.z += v2.z; v.w += v2.w;
                    }
                }
            }
            int mb = row >> 4, r = row & 15;
            int kb = lc >> 3, ch = (lc >> 2) & 1;
            int base = (kb * 8 + mb) * 128 + (r >> 3) + 2 * ch;
            int lbase = (r & 7) * 4;
            float vv[4] = {v.x, v.y, v.z, v.w};
#pragma unroll
            for (int j = 0; j < 4; j++) {
                uint32_t hib = to_tf32(vv[j]);
                float    hif = __uint_as_float(hib);
                uint32_t lob = to_tf32(vv[j] - hif);
                int addr = base + (lbase + j) * 4;
                Au[addr]            = hib;
                Au[A_FLOATS + addr] = lob;
            }
        }
        __syncthreads();

        // ---- mma over this chunk ----
#pragma unroll
        for (int s = 0; s < CHUNK / 8; s++) {
            int gs = (kc >> 3) + s;
            uint32_t afh[2][4], afl[2][4];
#pragma unroll
            for (int mf = 0; mf < 2; mf++) {
                int abase = (s * 8 + wm * 2 + mf) * 128 + lane * 4;
                uint4 hv = *reinterpret_cast<const uint4*>(Au + abase);
                uint4 lv = *reinterpret_cast<const uint4*>(Au + A_FLOATS + abase);
                afh[mf][0] = hv.x; afh[mf][1] = hv.y; afh[mf][2] = hv.z; afh[mf][3] = hv.w;
                afl[mf][0] = lv.x; afl[mf][1] = lv.y; afl[mf][2] = lv.z; afl[mf][3] = lv.w;
            }
#pragma unroll
            for (int nf = 0; nf < NFRAG; nf++) {
                int bbase = (gs * (N / 8) + wn * NFRAG + nf) * 64 + lane * 2;
                uint2 bh = *reinterpret_cast<const uint2*>(Bu + bbase);
                uint2 bl = *reinterpret_cast<const uint2*>(Bu + B_FLOATS + bbase);
                uint32_t bfh[2] = {bh.x, bh.y};
                uint32_t bfl[2] = {bl.x, bl.y};
#pragma unroll
                for (int mf = 0; mf < 2; mf++) {
                    mma_tf32(acc[mf][nf], afh[mf], bfl);   // Ah*Bl
                    mma_tf32(acc[mf][nf], afl[mf], bfh);   // Al*Bh
                    mma_tf32(acc[mf][nf], afh[mf], bfh);   // Ah*Bh
                }
            }
        }
    }

    // ---- epilogue: bias + relu + store + BN stats ----
    const int row_base = m0 + wm * 32 + g;
#pragma unroll
    for (int nf = 0; nf < NFRAG; nf++) {
        int col = wn * (N / 2) + nf * 8 + 2 * t;
        float2 b2 = *reinterpret_cast<const float2*>(bias + col);
        float cs0 = 0.f, cs1 = 0.f, cq0 = 0.f, cq1 = 0.f;
#pragma unroll
        for (int mf = 0; mf < 2; mf++) {
            int r1 = row_base + mf * 16;
            int r2 = r1 + 8;
            if (r1 < M) {
                float ox = fmaxf(acc[mf][nf][0] + b2.x, 0.f);
                float oy = fmaxf(acc[mf][nf][1] + b2.y, 0.f);
                *reinterpret_cast<float2*>(H + (size_t)r1 * N + col) = make_float2(ox, oy);
                cs0 += ox; cs1 += oy; cq0 += ox * ox; cq1 += oy * oy;
            }
            if (r2 < M) {
                float ox = fmaxf(acc[mf][nf][2] + b2.x, 0.f);
                float oy = fmaxf(acc[mf][nf][3] + b2.y, 0.f);
                *reinterpret_cast<float2*>(H + (size_t)r2 * N + col) = make_float2(ox, oy);
                cs0 += ox; cs1 += oy; cq0 += ox * ox; cq1 += oy * oy;
            }
        }
        atomicAdd(&s_sum[col],     cs0);
        atomicAdd(&s_sum[col + 1], cs1);
        atomicAdd(&s_sq [col],     cq0);
        atomicAdd(&s_sq [col + 1], cq1);
    }
    __syncthreads();
    for (int i = tid; i < N; i += 256) {
        atomicAdd(gsum + i, s_sum[i]);
        atomicAdd(gsq  + i, s_sq[i]);
    }
}

// ================= BN finalize =================
__global__ void finalize_kernel(const float* __restrict__ gsum,
                                const float* __restrict__ gsumsq,
                                const float* __restrict__ g,
                                const float* __restrict__ beta,
                                float* __restrict__ scale,
                                float* __restrict__ shift,
                                int BNc, int M)
{
    int t = threadIdx.x;
    if (t < BNc) {
        float invM = 1.0f / (float)M;
        float mu   = gsum[t] * invM;
        float var  = gsumsq[t] * invM - mu * mu;
        float inv  = rsqrtf(var + 1e-5f);
        float sc   = g[t] * inv;
        scale[t] = sc;
        shift[t] = fmaf(-mu, sc, beta[t]);
    }
}

// ================= final output normalize =================
__global__ void norm_kernel(const float* __restrict__ Hin,
                            const float* __restrict__ scale,
                            const float* __restrict__ shift,
                            float* __restrict__ out, int n4, int cols4)
{
    int i = blockIdx.x * blockDim.x + threadIdx.x;
    if (i >= n4) return;
    int c4 = (i % cols4) * 4;
    float4 v  = reinterpret_cast<const float4*>(Hin)[i];
    float4 sc = *reinterpret_cast<const float4*>(scale + c4);
    float4 sh = *reinterpret_cast<const float4*>(shift + c4);
    float4 r;
    r.x = fmaf(v.x, sc.x, sh.x);
    r.y = fmaf(v.y, sc.y, sh.y);
    r.z = fmaf(v.z, sc.z, sh.z);
    r.w = fmaf(v.w, sc.w, sh.w);
    reinterpret_cast<float4*>(out)[i] = r;
}

// ================= host =================
extern "C" void kernel_launch(void* const* d_in, const int* in_sizes, int n_in,
                              void* d_out, int out_size)
{
    const float* x   = (const float*)d_in[0];
    const float* ea  = (const float*)d_in[1];
    const int*   ei  = (const int*)  d_in[2];
    const float* lw  = (const float*)d_in[3];
    const float* lb  = (const float*)d_in[4];
    const float* w1  = (const float*)d_in[5];
    const float* b1  = (const float*)d_in[6];
    const float* g1  = (const float*)d_in[7];
    const float* be1 = (const float*)d_in[8];
    const float* w2  = (const float*)d_in[9];
    const float* b2  = (const float*)d_in[10];
    const float* g2  = (const float*)d_in[11];
    const float* be2 = (const float*)d_in[12];
    const float* w3  = (const float*)d_in[13];
    const float* b3  = (const float*)d_in[14];
    const float* g3  = (const float*)d_in[15];
    const float* be3 = (const float*)d_in[16];
    const float* w4  = (const float*)d_in[17];
    const float* b4  = (const float*)d_in[18];
    const float* g4  = (const float*)d_in[19];
    const float* be4 = (const float*)d_in[20];
    const float* w5  = (const float*)d_in[21];
    const float* b5  = (const float*)d_in[22];
    const float* g5  = (const float*)d_in[23];
    const float* be5 = (const float*)d_in[24];
    float* out = (float*)d_out;

    const int* srcp = ei;
    const int* dstp = ei + NE;

    float *agg, *h1, *h2, *h3, *h4, *h5, *sum, *sq, *scb, *shb;
    cudaGetSymbolAddress((void**)&agg, g_agg);
    cudaGetSymbolAddress((void**)&h1,  g_h1);
    cudaGetSymbolAddress((void**)&h2,  g_h2);
    cudaGetSymbolAddress((void**)&h3,  g_h3);
    cudaGetSymbolAddress((void**)&h4,  g_h4);
    cudaGetSymbolAddress((void**)&h5,  g_h5);
    cudaGetSymbolAddress((void**)&sum, g_sum);
    cudaGetSymbolAddress((void**)&sq,  g_sq);
    cudaGetSymbolAddress((void**)&scb, g_sc);
    cudaGetSymbolAddress((void**)&shb, g_sh);

    float* sc1 = scb + 0 * 96; float* sh1 = shb + 0 * 96;
    float* sc2 = scb + 1 * 96; float* sh2 = shb + 1 * 96;
    float* sc3 = scb + 2 * 96; float* sh3 = shb + 2 * 96;
    float* sc4 = scb + 3 * 96; float* sh4 = shb + 3 * 96;
    float* sc5 = scb + 4 * 96; float* sh5 = shb + 4 * 96;

    const int M = NN;
    const int gblocks = (M + 127) / 128;          // 391
    const int eblocks = (int)(((long long)NE * 24 + 255) / 256);

    // dynamic smem: 2*A + 2*B floats
    const int SM_96_96  = (2 * 128 * 96 + 2 * 96  * 96) * 4;   // 172032
    const int SM_64_96  = (2 * 128 * 96 + 2 * 96  * 64) * 4;   // 147456
    const int SM_96_160 = (2 * 128 * 32 + 2 * 160 * 96) * 4;   // 155648
    const int SM_16_96  = (2 * 128 * 96 + 2 * 96  * 16) * 4;   // 110592
    cudaFuncSetAttribute(gemm_mma<96, 96>,  cudaFuncAttributeMaxDynamicSharedMemorySize, SM_96_96);
    cudaFuncSetAttribute(gemm_mma<64, 96>,  cudaFuncAttributeMaxDynamicSharedMemorySize, SM_64_96);
    cudaFuncSetAttribute(gemm_mma<96, 160>, cudaFuncAttributeMaxDynamicSharedMemorySize, SM_96_160);
    cudaFuncSetAttribute(gemm_mma<16, 96>,  cudaFuncAttributeMaxDynamicSharedMemorySize, SM_16_96);

    // ---- conv1 ----
    cudaMemsetAsync(agg, 0, sizeof(float) * NN * 96, 0);
    edge_kernel<<<eblocks, 256>>>(x, nullptr, nullptr, ea, srcp, dstp, lw, lb, agg);
    cudaMemsetAsync(sum, 0, 96 * sizeof(float), 0);
    cudaMemsetAsync(sq,  0, 96 * sizeof(float), 0);
    gemm_mma<96, 96><<<gblocks, 256, SM_96_96>>>(x, nullptr, nullptr, agg,
                                                 nullptr, nullptr, nullptr, 96,
                                                 w1, b1, h1, sum, sq, M);
    finalize_kernel<<<1, 96>>>(sum, sq, g1, be1, sc1, sh1, 96, M);

    // ---- conv2 ----
    cudaMemsetAsync(agg, 0, sizeof(float) * NN * 96, 0);
    edge_kernel<<<eblocks, 256>>>(h1, sc1, sh1, ea, srcp, dstp, lw, lb, agg);
    cudaMemsetAsync(sum, 0, 96 * sizeof(float), 0);
    cudaMemsetAsync(sq,  0, 96 * sizeof(float), 0);
    gemm_mma<64, 96><<<gblocks, 256, SM_64_96>>>(h1, sc1, sh1, agg,
                                                 nullptr, nullptr, nullptr, 96,
                                                 w2, b2, h2, sum, sq, M);
    finalize_kernel<<<1, 64>>>(sum, sq, g2, be2, sc2, sh2, 64, M);

    // ---- lin1: concat(affine(h1), affine(h2)) @ w3 ----
    cudaMemsetAsync(sum, 0, 96 * sizeof(float), 0);
    cudaMemsetAsync(sq,  0, 96 * sizeof(float), 0);
    gemm_mma<96, 160><<<gblocks, 256, SM_96_160>>>(h1, sc1, sh1, nullptr,
                                                   h2, sc2, sh2, 96,
                                                   w3, b3, h3, sum, sq, M);
    finalize_kernel<<<1, 96>>>(sum, sq, g3, be3, sc3, sh3, 96, M);

    // ---- mlp1a ----
    cudaMemsetAsync(sum, 0, 96 * sizeof(float), 0);
    cudaMemsetAsync(sq,  0, 96 * sizeof(float), 0);
    gemm_mma<96, 96><<<gblocks, 256, SM_96_96>>>(h3, sc3, sh3, nullptr,
                                                 nullptr, nullptr, nullptr, 96,
                                                 w4, b4, h4, sum, sq, M);
    finalize_kernel<<<1, 96>>>(sum, sq, g4, be4, sc4, sh4, 96, M);

    // ---- mlp1b -> output ----
    cudaMemsetAsync(sum, 0, 96 * sizeof(float), 0);
    cudaMemsetAsync(sq,  0, 96 * sizeof(float), 0);
    gemm_mma<16, 96><<<gblocks, 256, SM_16_96>>>(h4, sc4, sh4, nullptr,
                                                 nullptr, nullptr, nullptr, 96,
                                                 w5, b5, h5, sum, sq, M);
    finalize_kernel<<<1, 16>>>(sum, sq, g5, be5, sc5, sh5, 16, M);
    norm_kernel<<<(M * 4 + 255) / 256, 256>>>(h5, sc5, sh5, out, M * 4, 4);

    (void)in_sizes; (void)n_in; (void)out_size;
}

// round 7
// speedup vs baseline: 1.0755x; 1.0755x over previous
#include <cuda_runtime.h>
#include <cstdint>

#define NN 50000
#define NE 800000

// ================= helpers =================
__device__ __forceinline__ uint32_t to_tf32(float x) {
    uint32_t r;
    asm("cvt.rna.tf32.f32 %0, %1;" : "=r"(r) : "f"(x));
    return r;
}

__device__ __forceinline__ void mma_tf32(float c[4], const uint32_t a[4], const uint32_t b[2]) {
    asm volatile(
        "mma.sync.aligned.m16n8k8.row.col.f32.tf32.tf32.f32 "
        "{%0,%1,%2,%3}, {%4,%5,%6,%7}, {%8,%9}, {%0,%1,%2,%3};"
        : "+f"(c[0]), "+f"(c[1]), "+f"(c[2]), "+f"(c[3])
        : "r"(a[0]), "r"(a[1]), "r"(a[2]), "r"(a[3]), "r"(b[0]), "r"(b[1]));
}

// ================= scratch =================
__device__ __align__(16) float g_agg[NN * 96];   // also reused as lin1 carry buffer
__device__ __align__(16) float g_h1 [NN * 96];
__device__ __align__(16) float g_h2 [NN * 64];
__device__ __align__(16) float g_h3 [NN * 96];
__device__ __align__(16) float g_h4 [NN * 96];
__device__ __align__(16) float g_h5 [NN * 16];
__device__ __align__(16) float g_sum[96];
__device__ __align__(16) float g_sq [96];
__device__ __align__(16) float g_sc [5][96];
__device__ __align__(16) float g_sh [5][96];

// ================= edge kernel (atomic scatter, proven) =================
__global__ void edge_kernel(const float* __restrict__ x,
                            const float* __restrict__ sc,
                            const float* __restrict__ sh,
                            const float* __restrict__ ea,
                            const int*   __restrict__ src,
                            const int*   __restrict__ dst,
                            const float* __restrict__ lw,
                            const float* __restrict__ lb,
                            float* __restrict__ agg)
{
    long long tid = (long long)blockIdx.x * blockDim.x + threadIdx.x;
    if (tid >= (long long)NE * 24) return;
    int i = (int)(tid / 24);
    int c = (int)(tid - (long long)i * 24);

    int   s = src[i];
    int   d = dst[i];
    float a = ea[i];

    float4 lw4 = reinterpret_cast<const float4*>(lw)[c];
    float4 lb4 = reinterpret_cast<const float4*>(lb)[c];
    float4 xv  = reinterpret_cast<const float4*>(x + (size_t)s * 96)[c];
    if (sc != nullptr) {
        float4 sc4 = reinterpret_cast<const float4*>(sc)[c];
        float4 sh4 = reinterpret_cast<const float4*>(sh)[c];
        xv.x = fmaf(xv.x, sc4.x, sh4.x);
        xv.y = fmaf(xv.y, sc4.y, sh4.y);
        xv.z = fmaf(xv.z, sc4.z, sh4.z);
        xv.w = fmaf(xv.w, sc4.w, sh4.w);
    }

    float4 m;
    m.x = fmaxf(fmaf(a, lw4.x, lb4.x) + xv.x, 0.0f);
    m.y = fmaxf(fmaf(a, lw4.y, lb4.y) + xv.y, 0.0f);
    m.z = fmaxf(fmaf(a, lw4.z, lb4.z) + xv.z, 0.0f);
    m.w = fmaxf(fmaf(a, lw4.w, lb4.w) + xv.w, 0.0f);

    float* p = agg + (size_t)d * 96 + c * 4;
    asm volatile("red.global.add.v4.f32 [%0], {%1, %2, %3, %4};"
                 :: "l"(p), "f"(m.x), "f"(m.y), "f"(m.z), "f"(m.w) : "memory");
}

// ================= tf32x3 mma.sync GEMM =================
// acc = In[M,K] @ W[K,N];  In row = affine(A) (+ Aadd).
// FINAL:  H = relu(acc + Cin + bias), column sum/sumsq -> gsum/gsq.
// !FINAL: H = acc (raw carry for split-K accumulation).
// A in SMEM as fp32 (fragment-permuted); hi/lo split in registers.
// B in SMEM as hi/lo tf32, interleaved per 128-word fragment block.
template<int N, int K, int WMW, int WNW, bool FINAL>
__global__ void __launch_bounds__(256, 2)
gemm_mma(const float* __restrict__ A,
         const float* __restrict__ scA, const float* __restrict__ shA,
         const float* __restrict__ Aadd,
         const float* __restrict__ Cin,
         const float* __restrict__ W, const float* __restrict__ bias,
         float* __restrict__ H,
         float* __restrict__ gsum, float* __restrict__ gsq,
         int M)
{
    constexpr int BM = WMW * 32;
    constexpr int NFRAG = N / WNW / 8;
    constexpr int A_FLOATS = BM * K;
    constexpr int KSTEPS = K / 8;

    extern __shared__ float smem[];
    float* As = smem;                              // fp32, permuted
    float* Bs = smem + A_FLOATS;                   // hi/lo interleaved blocks
    __shared__ float s_sum[N];
    __shared__ float s_sq [N];

    const int tid  = threadIdx.x;
    const int wid  = tid >> 5;
    const int lane = tid & 31;
    const int wm   = wid % WMW;
    const int wn   = wid / WMW;
    const int g    = lane >> 2;
    const int t    = lane & 3;
    const int m0   = blockIdx.x * BM;

    if constexpr (FINAL) {
        for (int i = tid; i < N; i += 256) { s_sum[i] = 0.f; s_sq[i] = 0.f; }
    }

    // ---- A prologue: affine / add, plain fp32, permuted scatter ----
    constexpr int KC4 = K / 4;
    for (int i = tid; i < BM * KC4; i += 256) {
        int row = i / KC4;
        int gc  = (i % KC4) * 4;
        int grow = m0 + row;
        float4 v = make_float4(0.f, 0.f, 0.f, 0.f);
        if (grow < M) {
            v = *reinterpret_cast<const float4*>(A + (size_t)grow * K + gc);
            if (scA != nullptr) {
                float4 s4 = *reinterpret_cast<const float4*>(scA + gc);
                float4 h4 = *reinterpret_cast<const float4*>(shA + gc);
                v.x = fmaf(v.x, s4.x, h4.x); v.y = fmaf(v.y, s4.y, h4.y);
                v.z = fmaf(v.z, s4.z, h4.z); v.w = fmaf(v.w, s4.w, h4.w);
            }
            if (Aadd != nullptr) {
                float4 v2 = *reinterpret_cast<const float4*>(Aadd + (size_t)grow * K + gc);
                v.x += v2.x; v.y += v2.y; v.z += v2.z; v.w += v2.w;
            }
        }
        int mb = row >> 4, r = row & 15;
        int kb = gc >> 3, ch = (gc >> 2) & 1;
        int base = (kb * (BM / 16) + mb) * 128 + (r >> 3) + 2 * ch;
        int lbase = (r & 7) * 4;
        As[base + (lbase + 0) * 4] = v.x;
        As[base + (lbase + 1) * 4] = v.y;
        As[base + (lbase + 2) * 4] = v.z;
        As[base + (lbase + 3) * 4] = v.w;
    }

    // ---- B prologue: W^T hi/lo, interleaved fragment blocks ----
    uint32_t* Bu = reinterpret_cast<uint32_t*>(Bs);
    constexpr int NC4 = N / 4;
    for (int i = tid; i < K * NC4; i += 256) {
        int k  = i / NC4;
        int n0 = (i % NC4) * 4;
        float4 v = *reinterpret_cast<const float4*>(W + (size_t)k * N + n0);
        float vv[4] = {v.x, v.y, v.z, v.w};
        int kb = k >> 3, kk = k & 7;
        int nb = n0 >> 3, nn0 = n0 & 7;
        int base = (kb * (N / 8) + nb) * 128 + (kk >> 2);
#pragma unroll
        for (int j = 0; j < 4; j++) {
            uint32_t hib = to_tf32(vv[j]);
            float    hif = __uint_as_float(hib);
            uint32_t lob = to_tf32(vv[j] - hif);
            int addr = base + ((nn0 + j) * 4 + (kk & 3)) * 4;
            Bu[addr]     = hib;      // words 0,1 = hi(b0,b1)
            Bu[addr + 2] = lob;      // words 2,3 = lo(b0,b1)
        }
    }
    __syncthreads();

    // ---- accumulators ----
    float acc[2][NFRAG][4];
#pragma unroll
    for (int mf = 0; mf < 2; mf++)
#pragma unroll
        for (int nf = 0; nf < NFRAG; nf++)
#pragma unroll
            for (int q = 0; q < 4; q++) acc[mf][nf][q] = 0.f;

    // ---- mainloop ----
#pragma unroll
    for (int s = 0; s < KSTEPS; s++) {
        uint32_t afh[2][4], afl[2][4];
#pragma unroll
        for (int mf = 0; mf < 2; mf++) {
            const float4 av = *reinterpret_cast<const float4*>(
                As + (s * (BM / 16) + wm * 2 + mf) * 128 + lane * 4);
            float fv[4] = {av.x, av.y, av.z, av.w};
#pragma unroll
            for (int j = 0; j < 4; j++) {
                uint32_t hib = to_tf32(fv[j]);
                afh[mf][j] = hib;
                afl[mf][j] = to_tf32(fv[j] - __uint_as_float(hib));
            }
        }
#pragma unroll
        for (int nf = 0; nf < NFRAG; nf++) {
            int bbase = (s * (N / 8) + wn * NFRAG + nf) * 128 + lane * 4;
            uint4 bv = *reinterpret_cast<const uint4*>(Bu + bbase);
            uint32_t bfh[2] = {bv.x, bv.y};
            uint32_t bfl[2] = {bv.z, bv.w};
#pragma unroll
            for (int mf = 0; mf < 2; mf++) {
                mma_tf32(acc[mf][nf], afh[mf], bfl);
                mma_tf32(acc[mf][nf], afl[mf], bfh);
                mma_tf32(acc[mf][nf], afh[mf], bfh);
            }
        }
    }

    // ---- epilogue ----
    const int row_base = m0 + wm * 32 + g;
#pragma unroll
    for (int nf = 0; nf < NFRAG; nf++) {
        int col = wn * (N / WNW) + nf * 8 + 2 * t;
        float2 b2 = make_float2(0.f, 0.f);
        if constexpr (FINAL) b2 = *reinterpret_cast<const float2*>(bias + col);
        float cs0 = 0.f, cs1 = 0.f, cq0 = 0.f, cq1 = 0.f;
#pragma unroll
        for (int mf = 0; mf < 2; mf++) {
#pragma unroll
            for (int rr = 0; rr < 2; rr++) {
                int row = row_base + mf * 16 + rr * 8;
                float a0 = acc[mf][nf][2 * rr];
                float a1 = acc[mf][nf][2 * rr + 1];
                if (row < M) {
                    if constexpr (FINAL) {
                        if (Cin != nullptr) {
                            float2 cv = *reinterpret_cast<const float2*>(Cin + (size_t)row * N + col);
                            a0 += cv.x; a1 += cv.y;
                        }
                        float ox = fmaxf(a0 + b2.x, 0.f);
                        float oy = fmaxf(a1 + b2.y, 0.f);
                        *reinterpret_cast<float2*>(H + (size_t)row * N + col) = make_float2(ox, oy);
                        cs0 += ox; cs1 += oy; cq0 += ox * ox; cq1 += oy * oy;
                    } else {
                        *reinterpret_cast<float2*>(H + (size_t)row * N + col) = make_float2(a0, a1);
                    }
                }
            }
        }
        if constexpr (FINAL) {
            atomicAdd(&s_sum[col],     cs0);
            atomicAdd(&s_sum[col + 1], cs1);
            atomicAdd(&s_sq [col],     cq0);
            atomicAdd(&s_sq [col + 1], cq1);
        }
    }
    if constexpr (FINAL) {
        __syncthreads();
        for (int i = tid; i < N; i += 256) {
            atomicAdd(gsum + i, s_sum[i]);
            atomicAdd(gsq  + i, s_sq[i]);
        }
    }
}

// ================= BN finalize =================
__global__ void finalize_kernel(const float* __restrict__ gsum,
                                const float* __restrict__ gsumsq,
                                const float* __restrict__ g,
                                const float* __restrict__ beta,
                                float* __restrict__ scale,
                                float* __restrict__ shift,
                                int BNc, int M)
{
    int t = threadIdx.x;
    if (t < BNc) {
        float invM = 1.0f / (float)M;
        float mu   = gsum[t] * invM;
        float var  = gsumsq[t] * invM - mu * mu;
        float inv  = rsqrtf(var + 1e-5f);
        float sc   = g[t] * inv;
        scale[t] = sc;
        shift[t] = fmaf(-mu, sc, beta[t]);
    }
}

// ================= final output normalize =================
__global__ void norm_kernel(const float* __restrict__ Hin,
                            const float* __restrict__ scale,
                            const float* __restrict__ shift,
                            float* __restrict__ out, int n4, int cols4)
{
    int i = blockIdx.x * blockDim.x + threadIdx.x;
    if (i >= n4) return;
    int c4 = (i % cols4) * 4;
    float4 v  = reinterpret_cast<const float4*>(Hin)[i];
    float4 sc = *reinterpret_cast<const float4*>(scale + c4);
    float4 sh = *reinterpret_cast<const float4*>(shift + c4);
    float4 r;
    r.x = fmaf(v.x, sc.x, sh.x);
    r.y = fmaf(v.y, sc.y, sh.y);
    r.z = fmaf(v.z, sc.z, sh.z);
    r.w = fmaf(v.w, sc.w, sh.w);
    reinterpret_cast<float4*>(out)[i] = r;
}

// ================= host =================
extern "C" void kernel_launch(void* const* d_in, const int* in_sizes, int n_in,
                              void* d_out, int out_size)
{
    const float* x   = (const float*)d_in[0];
    const float* ea  = (const float*)d_in[1];
    const int*   ei  = (const int*)  d_in[2];
    const float* lw  = (const float*)d_in[3];
    const float* lb  = (const float*)d_in[4];
    const float* w1  = (const float*)d_in[5];
    const float* b1  = (const float*)d_in[6];
    const float* g1  = (const float*)d_in[7];
    const float* be1 = (const float*)d_in[8];
    const float* w2  = (const float*)d_in[9];
    const float* b2  = (const float*)d_in[10];
    const float* g2  = (const float*)d_in[11];
    const float* be2 = (const float*)d_in[12];
    const float* w3  = (const float*)d_in[13];
    const float* b3  = (const float*)d_in[14];
    const float* g3  = (const float*)d_in[15];
    const float* be3 = (const float*)d_in[16];
    const float* w4  = (const float*)d_in[17];
    const float* b4  = (const float*)d_in[18];
    const float* g4  = (const float*)d_in[19];
    const float* be4 = (const float*)d_in[20];
    const float* w5  = (const float*)d_in[21];
    const float* b5  = (const float*)d_in[22];
    const float* g5  = (const float*)d_in[23];
    const float* be5 = (const float*)d_in[24];
    float* out = (float*)d_out;

    const int* srcp = ei;
    const int* dstp = ei + NE;

    float *agg, *h1, *h2, *h3, *h4, *h5, *sum, *sq, *scb, *shb;
    cudaGetSymbolAddress((void**)&agg, g_agg);
    cudaGetSymbolAddress((void**)&h1,  g_h1);
    cudaGetSymbolAddress((void**)&h2,  g_h2);
    cudaGetSymbolAddress((void**)&h3,  g_h3);
    cudaGetSymbolAddress((void**)&h4,  g_h4);
    cudaGetSymbolAddress((void**)&h5,  g_h5);
    cudaGetSymbolAddress((void**)&sum, g_sum);
    cudaGetSymbolAddress((void**)&sq,  g_sq);
    cudaGetSymbolAddress((void**)&scb, g_sc);
    cudaGetSymbolAddress((void**)&shb, g_sh);

    float* sc1 = scb + 0 * 96; float* sh1 = shb + 0 * 96;
    float* sc2 = scb + 1 * 96; float* sh2 = shb + 1 * 96;
    float* sc3 = scb + 2 * 96; float* sh3 = shb + 2 * 96;
    float* sc4 = scb + 3 * 96; float* sh4 = shb + 3 * 96;
    float* sc5 = scb + 4 * 96; float* sh5 = shb + 4 * 96;

    const int M = NN;
    const int eblocks = (int)(((long long)NE * 24 + 255) / 256);
    const int gb64  = (M + 63) / 64;     // 782
    const int gb128 = (M + 127) / 128;   // 391

    const int SM_96_96 = (64 * 96  + 2 * 96 * 96) * 4;   // 98304
    const int SM_64_96 = (64 * 96  + 2 * 96 * 64) * 4;   // 73728
    const int SM_96_64 = (64 * 64  + 2 * 64 * 96) * 4;   // 65536
    const int SM_16_96 = (128 * 96 + 2 * 96 * 16) * 4;   // 61440
    cudaFuncSetAttribute((const void*)gemm_mma<96, 96, 2, 4, true >, cudaFuncAttributeMaxDynamicSharedMemorySize, SM_96_96);
    cudaFuncSetAttribute((const void*)gemm_mma<64, 96, 2, 4, true >, cudaFuncAttributeMaxDynamicSharedMemorySize, SM_64_96);
    cudaFuncSetAttribute((const void*)gemm_mma<96, 96, 2, 4, false>, cudaFuncAttributeMaxDynamicSharedMemorySize, SM_96_96);
    cudaFuncSetAttribute((const void*)gemm_mma<96, 64, 2, 4, true >, cudaFuncAttributeMaxDynamicSharedMemorySize, SM_96_64);
    cudaFuncSetAttribute((const void*)gemm_mma<16, 96, 4, 2, true >, cudaFuncAttributeMaxDynamicSharedMemorySize, SM_16_96);

    // ---- conv1 ----
    cudaMemsetAsync(agg, 0, sizeof(float) * NN * 96, 0);
    edge_kernel<<<eblocks, 256>>>(x, nullptr, nullptr, ea, srcp, dstp, lw, lb, agg);
    cudaMemsetAsync(sum, 0, 96 * sizeof(float), 0);
    cudaMemsetAsync(sq,  0, 96 * sizeof(float), 0);
    gemm_mma<96, 96, 2, 4, true><<<gb64, 256, SM_96_96>>>(
        x, nullptr, nullptr, agg, nullptr, w1, b1, h1, sum, sq, M);
    finalize_kernel<<<1, 96>>>(sum, sq, g1, be1, sc1, sh1, 96, M);

    // ---- conv2 ----
    cudaMemsetAsync(agg, 0, sizeof(float) * NN * 96, 0);
    edge_kernel<<<eblocks, 256>>>(h1, sc1, sh1, ea, srcp, dstp, lw, lb, agg);
    cudaMemsetAsync(sum, 0, 96 * sizeof(float), 0);
    cudaMemsetAsync(sq,  0, 96 * sizeof(float), 0);
    gemm_mma<64, 96, 2, 4, true><<<gb64, 256, SM_64_96>>>(
        h1, sc1, sh1, agg, nullptr, w2, b2, h2, sum, sq, M);
    finalize_kernel<<<1, 64>>>(sum, sq, g2, be2, sc2, sh2, 64, M);

    // ---- lin1: split-K concat.  pass1: affine(h1)@W3[0:96] -> agg (raw) ----
    gemm_mma<96, 96, 2, 4, false><<<gb64, 256, SM_96_96>>>(
        h1, sc1, sh1, nullptr, nullptr, w3, nullptr, agg, nullptr, nullptr, M);
    // pass2: affine(h2)@W3[96:160] + carry + bias -> relu+stats -> h3
    cudaMemsetAsync(sum, 0, 96 * sizeof(float), 0);
    cudaMemsetAsync(sq,  0, 96 * sizeof(float), 0);
    gemm_mma<96, 64, 2, 4, true><<<gb64, 256, SM_96_64>>>(
        h2, sc2, sh2, nullptr, agg, w3 + 96 * 96, b3, h3, sum, sq, M);
    finalize_kernel<<<1, 96>>>(sum, sq, g3, be3, sc3, sh3, 96, M);

    // ---- mlp1a ----
    cudaMemsetAsync(sum, 0, 96 * sizeof(float), 0);
    cudaMemsetAsync(sq,  0, 96 * sizeof(float), 0);
    gemm_mma<96, 96, 2, 4, true><<<gb64, 256, SM_96_96>>>(
        h3, sc3, sh3, nullptr, nullptr, w4, b4, h4, sum, sq, M);
    finalize_kernel<<<1, 96>>>(sum, sq, g4, be4, sc4, sh4, 96, M);

    // ---- mlp1b -> output ----
    cudaMemsetAsync(sum, 0, 96 * sizeof(float), 0);
    cudaMemsetAsync(sq,  0, 96 * sizeof(float), 0);
    gemm_mma<16, 96, 4, 2, true><<<gb128, 256, SM_16_96>>>(
        h4, sc4, sh4, nullptr, nullptr, w5, b5, h5, sum, sq, M);
    finalize_kernel<<<1, 16>>>(sum, sq, g5, be5, sc5, sh5, 16, M);
    norm_kernel<<<(M * 4 + 255) / 256, 256>>>(h5, sc5, sh5, out, M * 4, 4);

    (void)in_sizes; (void)n_in; (void)out_size;
}

// round 8
// speedup vs baseline: 1.4187x; 1.3191x over previous
#include <cuda_runtime.h>
#include <cstdint>

#define NN 50000
#define NE 800000

// ================= scratch =================
__device__ __align__(16) float g_agg[NN * 96];
__device__ __align__(16) float g_h1 [NN * 96];
__device__ __align__(16) float g_h2 [NN * 64];
__device__ __align__(16) float g_h3 [NN * 96];
__device__ __align__(16) float g_h4 [NN * 96];
__device__ __align__(16) float g_h5 [NN * 16];
__device__ __align__(16) float g_sum[96];
__device__ __align__(16) float g_sq [96];
__device__ __align__(16) float g_sc [5][96];
__device__ __align__(16) float g_sh [5][96];
// CSR scratch
__device__ int   g_deg      [NN];
__device__ int   g_row_start[NN];
__device__ int   g_pos      [NN];
__device__ int   g_csr_src  [NE];
__device__ float g_csr_ea   [NE];

// ================= CSR build (proven R2) =================
__global__ void hist_kernel(const int* __restrict__ dst, int* __restrict__ deg)
{
    int i = blockIdx.x * blockDim.x + threadIdx.x;
    if (i < NE) atomicAdd(&deg[dst[i]], 1);
}

__global__ void scan_kernel(const int* __restrict__ deg,
                            int* __restrict__ row_start,
                            int* __restrict__ pos)
{
    constexpr int T = 1024;
    constexpr int CH = (NN + T - 1) / T;
    __shared__ int warp_sums[32];
    int t = threadIdx.x;
    int base = t * CH;

    int s = 0;
    for (int i = 0; i < CH; i++) {
        int idx = base + i;
        if (idx < NN) s += deg[idx];
    }
    int lane = t & 31, wid = t >> 5;
    int v = s;
#pragma unroll
    for (int o = 1; o < 32; o <<= 1) {
        int u = __shfl_up_sync(0xffffffff, v, o);
        if (lane >= o) v += u;
    }
    if (lane == 31) warp_sums[wid] = v;
    __syncthreads();
    if (wid == 0) {
        int w = warp_sums[lane];
#pragma unroll
        for (int o = 1; o < 32; o <<= 1) {
            int u = __shfl_up_sync(0xffffffff, w, o);
            if (lane >= o) w += u;
        }
        warp_sums[lane] = w;
    }
    __syncthreads();
    int excl = v - s + (wid > 0 ? warp_sums[wid - 1] : 0);

    int running = excl;
    for (int i = 0; i < CH; i++) {
        int idx = base + i;
        if (idx < NN) {
            row_start[idx] = running;
            pos[idx]       = running;
            running += deg[idx];
        }
    }
}

__global__ void scatter_kernel(const int* __restrict__ src,
                               const int* __restrict__ dst,
                               const float* __restrict__ ea,
                               int* __restrict__ pos,
                               int* __restrict__ csr_src,
                               float* __restrict__ csr_ea)
{
    int i = blockIdx.x * blockDim.x + threadIdx.x;
    if (i >= NE) return;
    int slot = atomicAdd(&pos[dst[i]], 1);
    csr_src[slot] = src[i];
    csr_ea [slot] = ea[i];
}

// ================= CSR gather aggregation =================
// agg[n][:] = sum_e relu(affine(x[src_e]) + (a_e*lw + lb))
// Warp per node; lane owns cols {l, l+32, l+64}; edge idx/attr broadcast.
__global__ void __launch_bounds__(256)
aggregate_kernel(const float* __restrict__ xin,
                 const float* __restrict__ sc,
                 const float* __restrict__ sh,
                 const float* __restrict__ lw,
                 const float* __restrict__ lb,
                 const int* __restrict__ row_start,
                 const int* __restrict__ deg,
                 const int* __restrict__ csr_src,
                 const float* __restrict__ csr_ea,
                 float* __restrict__ agg)
{
    int w    = threadIdx.x >> 5;
    int lane = threadIdx.x & 31;
    int node = blockIdx.x * 8 + w;
    if (node >= NN) return;

    float lw0 = lw[lane], lw1 = lw[lane + 32], lw2 = lw[lane + 64];
    float lb0 = lb[lane], lb1 = lb[lane + 32], lb2 = lb[lane + 64];
    float sc0 = 1.f, sc1 = 1.f, sc2 = 1.f;
    float sh0 = 0.f, sh1 = 0.f, sh2 = 0.f;
    if (sc != nullptr) {
        sc0 = sc[lane]; sc1 = sc[lane + 32]; sc2 = sc[lane + 64];
        sh0 = sh[lane]; sh1 = sh[lane + 32]; sh2 = sh[lane + 64];
    }

    int s0 = row_start[node];
    int d  = deg[node];

    float a0 = 0.f, a1 = 0.f, a2 = 0.f;
#pragma unroll 2
    for (int e = 0; e < d; e++) {
        int   s = __ldg(csr_src + s0 + e);    // broadcast (same addr all lanes)
        float a = __ldg(csr_ea  + s0 + e);
        const float* xr = xin + (size_t)s * 96;
        float x0 = __ldg(xr + lane);
        float x1 = __ldg(xr + lane + 32);
        float x2 = __ldg(xr + lane + 64);
        a0 += fmaxf(fmaf(x0, sc0, sh0) + fmaf(a, lw0, lb0), 0.f);
        a1 += fmaxf(fmaf(x1, sc1, sh1) + fmaf(a, lw1, lb1), 0.f);
        a2 += fmaxf(fmaf(x2, sc2, sh2) + fmaf(a, lw2, lb2), 0.f);
    }
    float* ar = agg + (size_t)node * 96;
    ar[lane]      = a0;
    ar[lane + 32] = a1;
    ar[lane + 64] = a2;
}

// ================= fused GEMM + bias + ReLU + BN stats (proven R2) =================
// input row = affine(A) (+ Aadd) for cols < K1, affine2(B2) for cols >= K1
template<int BN, int TX, int TY, int TM>
__global__ void gemm_kernel(const float* __restrict__ A,
                            const float* __restrict__ scA,
                            const float* __restrict__ shA,
                            const float* __restrict__ Aadd,
                            const float* __restrict__ B2,
                            const float* __restrict__ scB,
                            const float* __restrict__ shB,
                            int K, int K1,
                            const float* __restrict__ W,
                            const float* __restrict__ bias,
                            float* __restrict__ H,
                            float* __restrict__ gsum,
                            float* __restrict__ gsumsq,
                            int M)
{
    constexpr int BK = 32;
    constexpr int BM = TY * TM;
    constexpr int THREADS = TX * TY;
    constexpr int S = BM + 4;

    __shared__ float At[BK][S];
    __shared__ float Wt[BK][BN];
    __shared__ float s_sum[BN];
    __shared__ float s_sq [BN];

    const int tid = threadIdx.x;
    const int tx  = tid % TX;
    const int ty  = tid / TX;
    const int m0  = blockIdx.x * BM;
    const int K2  = K - K1;

    for (int t = tid; t < BN; t += THREADS) { s_sum[t] = 0.f; s_sq[t] = 0.f; }

    float acc[TM][4];
#pragma unroll
    for (int i = 0; i < TM; i++) { acc[i][0]=0.f; acc[i][1]=0.f; acc[i][2]=0.f; acc[i][3]=0.f; }

    for (int kb = 0; kb < K; kb += BK) {
        for (int t = tid; t < BM * (BK / 4); t += THREADS) {
            int m  = t >> 3;
            int k4 = (t & 7) * 4;
            int row = m0 + m;
            float4 v = make_float4(0.f, 0.f, 0.f, 0.f);
            if (row < M) {
                int gc = kb + k4;
                if (B2 != nullptr && gc >= K1) {
                    int c2 = gc - K1;
                    v = *reinterpret_cast<const float4*>(B2 + (size_t)row * K2 + c2);
                    if (scB != nullptr) {
                        float4 sc4 = *reinterpret_cast<const float4*>(scB + c2);
                        float4 sh4 = *reinterpret_cast<const float4*>(shB + c2);
                        v.x = fmaf(v.x, sc4.x, sh4.x);
                        v.y = fmaf(v.y, sc4.y, sh4.y);
                        v.z = fmaf(v.z, sc4.z, sh4.z);
                        v.w = fmaf(v.w, sc4.w, sh4.w);
                    }
                } else {
                    v = *reinterpret_cast<const float4*>(A + (size_t)row * K1 + gc);
                    if (scA != nullptr) {
                        float4 sc4 = *reinterpret_cast<const float4*>(scA + gc);
                        float4 sh4 = *reinterpret_cast<const float4*>(shA + gc);
                        v.x = fmaf(v.x, sc4.x, sh4.x);
                        v.y = fmaf(v.y, sc4.y, sh4.y);
                        v.z = fmaf(v.z, sc4.z, sh4.z);
                        v.w = fmaf(v.w, sc4.w, sh4.w);
                    }
                    if (Aadd != nullptr) {
                        float4 v2 = *reinterpret_cast<const float4*>(Aadd + (size_t)row * K1 + gc);
                        v.x += v2.x; v.y += v2.y; v.z += v2.z; v.w += v2.w;
                    }
                }
            }
            At[k4 + 0][m] = v.x;
            At[k4 + 1][m] = v.y;
            At[k4 + 2][m] = v.z;
            At[k4 + 3][m] = v.w;
        }
        for (int t = tid; t < BK * (BN / 4); t += THREADS) {
            int k  = t / (BN / 4);
            int c4 = (t % (BN / 4)) * 4;
            float4 v = *reinterpret_cast<const float4*>(W + (size_t)(kb + k) * BN + c4);
            *reinterpret_cast<float4*>(&Wt[k][c4]) = v;
        }
        __syncthreads();

#pragma unroll 8
        for (int k = 0; k < BK; k++) {
            float4 wv = *reinterpret_cast<const float4*>(&Wt[k][tx * 4]);
            float av[TM];
            if constexpr (TM % 4 == 0) {
#pragma unroll
                for (int ii = 0; ii < TM / 4; ii++) {
                    float4 a4 = *reinterpret_cast<const float4*>(&At[k][ty * TM + ii * 4]);
                    av[ii*4+0] = a4.x; av[ii*4+1] = a4.y; av[ii*4+2] = a4.z; av[ii*4+3] = a4.w;
                }
            } else {
                float2 a2 = *reinterpret_cast<const float2*>(&At[k][ty * TM]);
                av[0] = a2.x; av[1] = a2.y;
            }
#pragma unroll
            for (int i = 0; i < TM; i++) {
                acc[i][0] = fmaf(av[i], wv.x, acc[i][0]);
                acc[i][1] = fmaf(av[i], wv.y, acc[i][1]);
                acc[i][2] = fmaf(av[i], wv.z, acc[i][2]);
                acc[i][3] = fmaf(av[i], wv.w, acc[i][3]);
            }
        }
        __syncthreads();
    }

    float4 b4 = *reinterpret_cast<const float4*>(bias + tx * 4);
    float csum[4] = {0.f, 0.f, 0.f, 0.f};
    float csq [4] = {0.f, 0.f, 0.f, 0.f};
#pragma unroll
    for (int i = 0; i < TM; i++) {
        int row = m0 + ty * TM + i;
        if (row < M) {
            float4 o;
            o.x = fmaxf(acc[i][0] + b4.x, 0.f);
            o.y = fmaxf(acc[i][1] + b4.y, 0.f);
            o.z = fmaxf(acc[i][2] + b4.z, 0.f);
            o.w = fmaxf(acc[i][3] + b4.w, 0.f);
            *reinterpret_cast<float4*>(H + (size_t)row * BN + tx * 4) = o;
            csum[0] += o.x; csum[1] += o.y; csum[2] += o.z; csum[3] += o.w;
            csq [0] += o.x * o.x; csq[1] += o.y * o.y; csq[2] += o.z * o.z; csq[3] += o.w * o.w;
        }
    }
    atomicAdd(&s_sum[tx * 4 + 0], csum[0]);
    atomicAdd(&s_sum[tx * 4 + 1], csum[1]);
    atomicAdd(&s_sum[tx * 4 + 2], csum[2]);
    atomicAdd(&s_sum[tx * 4 + 3], csum[3]);
    atomicAdd(&s_sq [tx * 4 + 0], csq[0]);
    atomicAdd(&s_sq [tx * 4 + 1], csq[1]);
    atomicAdd(&s_sq [tx * 4 + 2], csq[2]);
    atomicAdd(&s_sq [tx * 4 + 3], csq[3]);
    __syncthreads();
    for (int t = tid; t < BN; t += THREADS) {
        atomicAdd(gsum   + t, s_sum[t]);
        atomicAdd(gsumsq + t, s_sq[t]);
    }
}

// ================= BN finalize =================
__global__ void finalize_kernel(const float* __restrict__ gsum,
                                const float* __restrict__ gsumsq,
                                const float* __restrict__ g,
                                const float* __restrict__ beta,
                                float* __restrict__ scale,
                                float* __restrict__ shift,
                                int BNc, int M)
{
    int t = threadIdx.x;
    if (t < BNc) {
        float invM = 1.0f / (float)M;
        float mu   = gsum[t] * invM;
        float var  = gsumsq[t] * invM - mu * mu;
        float inv  = rsqrtf(var + 1e-5f);
        float sc   = g[t] * inv;
        scale[t] = sc;
        shift[t] = fmaf(-mu, sc, beta[t]);
    }
}

// ================= final output normalize =================
__global__ void norm_kernel(const float* __restrict__ Hin,
                            const float* __restrict__ scale,
                            const float* __restrict__ shift,
                            float* __restrict__ out, int n4, int cols4)
{
    int i = blockIdx.x * blockDim.x + threadIdx.x;
    if (i >= n4) return;
    int c4 = (i % cols4) * 4;
    float4 v  = reinterpret_cast<const float4*>(Hin)[i];
    float4 sc = *reinterpret_cast<const float4*>(scale + c4);
    float4 sh = *reinterpret_cast<const float4*>(shift + c4);
    float4 r;
    r.x = fmaf(v.x, sc.x, sh.x);
    r.y = fmaf(v.y, sc.y, sh.y);
    r.z = fmaf(v.z, sc.z, sh.z);
    r.w = fmaf(v.w, sc.w, sh.w);
    reinterpret_cast<float4*>(out)[i] = r;
}

// ================= host =================
extern "C" void kernel_launch(void* const* d_in, const int* in_sizes, int n_in,
                              void* d_out, int out_size)
{
    const float* x   = (const float*)d_in[0];
    const float* ea  = (const float*)d_in[1];
    const int*   ei  = (const int*)  d_in[2];
    const float* lw  = (const float*)d_in[3];
    const float* lb  = (const float*)d_in[4];
    const float* w1  = (const float*)d_in[5];
    const float* b1  = (const float*)d_in[6];
    const float* g1  = (const float*)d_in[7];
    const float* be1 = (const float*)d_in[8];
    const float* w2  = (const float*)d_in[9];
    const float* b2  = (const float*)d_in[10];
    const float* g2  = (const float*)d_in[11];
    const float* be2 = (const float*)d_in[12];
    const float* w3  = (const float*)d_in[13];
    const float* b3  = (const float*)d_in[14];
    const float* g3  = (const float*)d_in[15];
    const float* be3 = (const float*)d_in[16];
    const float* w4  = (const float*)d_in[17];
    const float* b4  = (const float*)d_in[18];
    const float* g4  = (const float*)d_in[19];
    const float* be4 = (const float*)d_in[20];
    const float* w5  = (const float*)d_in[21];
    const float* b5  = (const float*)d_in[22];
    const float* g5  = (const float*)d_in[23];
    const float* be5 = (const float*)d_in[24];
    float* out = (float*)d_out;

    const int* srcp = ei;
    const int* dstp = ei + NE;

    float *agg, *h1, *h2, *h3, *h4, *h5, *sum, *sq, *scb, *shb;
    int *deg, *row_start, *pos, *csr_src;
    float *csr_ea;
    cudaGetSymbolAddress((void**)&agg,       g_agg);
    cudaGetSymbolAddress((void**)&h1,        g_h1);
    cudaGetSymbolAddress((void**)&h2,        g_h2);
    cudaGetSymbolAddress((void**)&h3,        g_h3);
    cudaGetSymbolAddress((void**)&h4,        g_h4);
    cudaGetSymbolAddress((void**)&h5,        g_h5);
    cudaGetSymbolAddress((void**)&sum,       g_sum);
    cudaGetSymbolAddress((void**)&sq,        g_sq);
    cudaGetSymbolAddress((void**)&scb,       g_sc);
    cudaGetSymbolAddress((void**)&shb,       g_sh);
    cudaGetSymbolAddress((void**)&deg,       g_deg);
    cudaGetSymbolAddress((void**)&row_start, g_row_start);
    cudaGetSymbolAddress((void**)&pos,       g_pos);
    cudaGetSymbolAddress((void**)&csr_src,   g_csr_src);
    cudaGetSymbolAddress((void**)&csr_ea,    g_csr_ea);

    float* sc1 = scb + 0 * 96; float* sh1 = shb + 0 * 96;
    float* sc2 = scb + 1 * 96; float* sh2 = shb + 1 * 96;
    float* sc3 = scb + 2 * 96; float* sh3 = shb + 2 * 96;
    float* sc4 = scb + 3 * 96; float* sh4 = shb + 3 * 96;
    float* sc5 = scb + 4 * 96; float* sh5 = shb + 4 * 96;

    const int M = NN;
    const int eblk = (NE + 255) / 256;
    const int ablocks = (NN + 7) / 8;

    // ---- CSR build (shared by both convs) ----
    cudaMemsetAsync(deg, 0, NN * sizeof(int), 0);
    hist_kernel<<<eblk, 256>>>(dstp, deg);
    scan_kernel<<<1, 1024>>>(deg, row_start, pos);
    scatter_kernel<<<eblk, 256>>>(srcp, dstp, ea, pos, csr_src, csr_ea);

    // ---- conv1 ----
    aggregate_kernel<<<ablocks, 256>>>(x, nullptr, nullptr, lw, lb,
                                       row_start, deg, csr_src, csr_ea, agg);
    cudaMemsetAsync(sum, 0, 96 * sizeof(float), 0);
    cudaMemsetAsync(sq,  0, 96 * sizeof(float), 0);
    gemm_kernel<96, 24, 8, 8><<<(M + 63) / 64, 192>>>(x, nullptr, nullptr, agg,
                                                      nullptr, nullptr, nullptr,
                                                      96, 96, w1, b1, h1, sum, sq, M);
    finalize_kernel<<<1, 96>>>(sum, sq, g1, be1, sc1, sh1, 96, M);

    // ---- conv2 ----
    aggregate_kernel<<<ablocks, 256>>>(h1, sc1, sh1, lw, lb,
                                       row_start, deg, csr_src, csr_ea, agg);
    cudaMemsetAsync(sum, 0, 96 * sizeof(float), 0);
    cudaMemsetAsync(sq,  0, 96 * sizeof(float), 0);
    gemm_kernel<64, 16, 16, 4><<<(M + 63) / 64, 256>>>(h1, sc1, sh1, agg,
                                                       nullptr, nullptr, nullptr,
                                                       96, 96, w2, b2, h2, sum, sq, M);
    finalize_kernel<<<1, 64>>>(sum, sq, g2, be2, sc2, sh2, 64, M);

    // ---- lin1: concat(affine(h1), affine(h2)) @ w3 ----
    cudaMemsetAsync(sum, 0, 96 * sizeof(float), 0);
    cudaMemsetAsync(sq,  0, 96 * sizeof(float), 0);
    gemm_kernel<96, 24, 8, 8><<<(M + 63) / 64, 192>>>(h1, sc1, sh1, nullptr,
                                                      h2, sc2, sh2,
                                                      160, 96, w3, b3, h3, sum, sq, M);
    finalize_kernel<<<1, 96>>>(sum, sq, g3, be3, sc3, sh3, 96, M);

    // ---- mlp1a ----
    cudaMemsetAsync(sum, 0, 96 * sizeof(float), 0);
    cudaMemsetAsync(sq,  0, 96 * sizeof(float), 0);
    gemm_kernel<96, 24, 8, 8><<<(M + 63) / 64, 192>>>(h3, sc3, sh3, nullptr,
                                                      nullptr, nullptr, nullptr,
                                                      96, 96, w4, b4, h4, sum, sq, M);
    finalize_kernel<<<1, 96>>>(sum, sq, g4, be4, sc4, sh4, 96, M);

    // ---- mlp1b -> output ----
    cudaMemsetAsync(sum, 0, 96 * sizeof(float), 0);
    cudaMemsetAsync(sq,  0, 96 * sizeof(float), 0);
    gemm_kernel<16, 4, 32, 2><<<(M + 63) / 64, 128>>>(h4, sc4, sh4, nullptr,
                                                      nullptr, nullptr, nullptr,
                                                      96, 96, w5, b5, h5, sum, sq, M);
    finalize_kernel<<<1, 16>>>(sum, sq, g5, be5, sc5, sh5, 16, M);
    norm_kernel<<<(M * 4 + 255) / 256, 256>>>(h5, sc5, sh5, out, M * 4, 4);

    (void)in_sizes; (void)n_in; (void)out_size;
}